// round 16
// baseline (speedup 1.0000x reference)
#include <cuda_runtime.h>

#define C 512
#define NSEG 7          // 50176/7 = 7168 = 7*1024 -> guard-free fast path
#define NSEG_MAX 8
#define FULLMASK 0xffffffffu

// ---- scratch (no allocs allowed) -------------------------------------------
__device__ float g_part[C][NSEG_MAX];   // partial channel sums
__device__ float g_bv[C];
__device__ float g_xtmp[C];
__device__ float g_xsparse[C];
__device__ float g_scale[C];
__device__ float g_coeff;               // 0.05 / norm (or 0.05 if norm invalid)
__device__ unsigned g_ctr = 0;          // last-block election (never reset; modulo test)

// ---- K1: per-channel partial sums -------------------------------------------
// EXACT path: block=1024 threads, each thread 7 front-batched float4 loads.
// Each CTA's only successor-visible write is one g_part scalar, so it triggers
// PDL completion right after that store: the dependent grid's
// cudaGridDependencySynchronize clears on (all triggers + flush) instead of
// waiting for the full grid-end membar.
template <bool EXACT>
__global__ void k_channel_mean(const float* __restrict__ x, int n4, int seglen, int nseg) {
    const int c   = blockIdx.y;
    const int seg = blockIdx.x;
    const float4* xp = reinterpret_cast<const float4*>(x) + (size_t)c * n4 + (size_t)seg * seglen;

    float s;
    if (EXACT) {
        const int t = threadIdx.x;
        float4 v0 = __ldcs(xp + t);
        float4 v1 = __ldcs(xp + t + 1024);
        float4 v2 = __ldcs(xp + t + 2048);
        float4 v3 = __ldcs(xp + t + 3072);
        float4 v4 = __ldcs(xp + t + 4096);
        float4 v5 = __ldcs(xp + t + 5120);
        float4 v6 = __ldcs(xp + t + 6144);
        float a0 = (v0.x + v0.y) + (v0.z + v0.w);
        float a1 = (v1.x + v1.y) + (v1.z + v1.w);
        float a2 = (v2.x + v2.y) + (v2.z + v2.w);
        float a3 = (v3.x + v3.y) + (v3.z + v3.w);
        float a4 = (v4.x + v4.y) + (v4.z + v4.w);
        float a5 = (v5.x + v5.y) + (v5.z + v5.w);
        float a6 = (v6.x + v6.y) + (v6.z + v6.w);
        s = ((a0 + a1) + (a2 + a3)) + ((a4 + a5) + a6);
    } else {
        const int lim = min(seglen, n4 - seg * seglen);
        float s0 = 0.f, s1 = 0.f, s2 = 0.f, s3 = 0.f;
        for (int i = threadIdx.x; i < lim; i += 4 * blockDim.x) {
            const int i1 = i + blockDim.x, i2 = i + 2 * blockDim.x, i3 = i + 3 * blockDim.x;
            float4 v;
            v = __ldcs(xp + i);                  s0 += (v.x + v.y) + (v.z + v.w);
            if (i1 < lim) { v = __ldcs(xp + i1); s1 += (v.x + v.y) + (v.z + v.w); }
            if (i2 < lim) { v = __ldcs(xp + i2); s2 += (v.x + v.y) + (v.z + v.w); }
            if (i3 < lim) { v = __ldcs(xp + i3); s3 += (v.x + v.y) + (v.z + v.w); }
        }
        s = (s0 + s1) + (s2 + s3);
    }

    __shared__ float sm[32];
    #pragma unroll
    for (int o = 16; o; o >>= 1) s += __shfl_xor_sync(FULLMASK, s, o);
    const int lane = threadIdx.x & 31, w = threadIdx.x >> 5;
    if (lane == 0) sm[w] = s;
    __syncthreads();
    if (threadIdx.x == 0) {
        float t = 0.f;
        const int nw = blockDim.x >> 5;
        for (int k = 0; k < nw; k++) t += sm[k];
        g_part[c][seg] = t;
#if __CUDA_ARCH__ >= 900
        __threadfence();
        cudaTriggerProgrammaticLaunchCompletion();
#endif
    }
}

__device__ __forceinline__ float channel_avg(int ch, float inv_hw, int nseg) {
    float t = 0.f;
    #pragma unroll
    for (int k = 0; k < NSEG_MAX; k++)
        if (k < nseg) t += g_part[ch][k];
    return t * inv_hw;
}

// ---- 128-thread (4-warp) block reductions -----------------------------------
__device__ __forceinline__ float blk_sum128(float v, volatile float* sm) {
    #pragma unroll
    for (int o = 16; o; o >>= 1) v += __shfl_xor_sync(FULLMASK, v, o);
    const int lane = threadIdx.x & 31, w = threadIdx.x >> 5;
    if (lane == 0) sm[w] = v;
    __syncthreads();
    float r = (sm[0] + sm[1]) + (sm[2] + sm[3]);
    __syncthreads();
    return r;
}

__device__ __forceinline__ float blk_max128(float v, volatile float* sm) {
    #pragma unroll
    for (int o = 16; o; o >>= 1) v = fmaxf(v, __shfl_xor_sync(FULLMASK, v, o));
    const int lane = threadIdx.x & 31, w = threadIdx.x >> 5;
    if (lane == 0) sm[w] = v;
    __syncthreads();
    float r = fmaxf(fmaxf(sm[0], sm[1]), fmaxf(sm[2], sm[3]));
    __syncthreads();
    return r;
}

// ---- K2: matvec (512 blocks x 128 thr) + last-block stats ---------------------
// Implicit trigger (at exit): the successor (apply) depends on stats written by
// the LAST-finishing block, so early triggering here would be unsound.
__global__ void k_matvec_stats(const float* __restrict__ W, float inv_hw, int nseg) {
#if __CUDA_ARCH__ >= 900
    cudaGridDependencySynchronize();   // wait for mean grid (PDL)
#endif
    __shared__ float av[C];
    __shared__ float sm[4];
    __shared__ int   is_last;
    const int t = threadIdx.x;  // 128 threads

    #pragma unroll
    for (int j = t; j < C; j += 128) av[j] = channel_avg(j, inv_hw, nseg);
    __syncthreads();

    const int row = blockIdx.x;
    float4 wv = __ldg(reinterpret_cast<const float4*>(W + (size_t)row * C) + t);
    float s = wv.x * av[4*t] + wv.y * av[4*t+1] + wv.z * av[4*t+2] + wv.w * av[4*t+3];
    #pragma unroll
    for (int o = 16; o; o >>= 1) s += __shfl_xor_sync(FULLMASK, s, o);
    if ((t & 31) == 0) sm[t >> 5] = s;
    __syncthreads();
    if (t == 0) {
        g_bv[row] = (sm[0] + sm[1]) + (sm[2] + sm[3]);
        __threadfence();
        unsigned old = atomicAdd(&g_ctr, 1u);
        is_last = ((old & (C - 1)) == (C - 1)) ? 1 : 0;
    }
    __syncthreads();
    if (!is_last) return;

    // ---- stats: runs in the one block that finished last (sees all g_bv) ----
    __threadfence();
    float a[4], b[4];
    #pragma unroll
    for (int k = 0; k < 4; k++) {
        const int ch = t + 128 * k;
        a[k] = av[ch];
        b[k] = g_bv[ch];
    }

    const float inh = blk_sum128((b[0] + b[1]) + (b[2] + b[3]), sm) * (1.0f / (float)C);

    float xt[4], lmax = -3.4e38f;
    #pragma unroll
    for (int k = 0; k < 4; k++) {
        float v = a[k] + b[k] - 2.0f * inh;
        xt[k] = v > 0.f ? v : 0.f;
        lmax = fmaxf(lmax, xt[k]);
    }
    const float thr = blk_max128(lmax, sm) * 0.9f;

    float xs[4];
    float lst2 = 0.f, lss2 = 0.f, lsd2 = 0.f;
    #pragma unroll
    for (int k = 0; k < 4; k++) {
        const int ch = t + 128 * k;
        xs[k] = (xt[k] < thr) ? 0.f : xt[k];
        g_xtmp[ch]    = xt[k];
        g_xsparse[ch] = xs[k];
        g_scale[ch]   = xt[k] / (a[k] + 1e-12f);
        lst2 += xt[k] * xt[k];
        lss2 += xs[k] * xs[k];
        const float ts = xt[k] * xs[k];
        lsd2 += ts * ts;
    }
    const float st2 = blk_sum128(lst2, sm);
    const float ss2 = blk_sum128(lss2, sm);
    const float sd2 = blk_sum128(lsd2, sm);

    if (t == 0) {
        const float n2 = st2 * ss2 - sd2;             // ||outer zero-diag||_F^2
        const float n  = sqrtf(n2);
        float coeff = 0.05f;
        if (isfinite(n) && n > 0.f) coeff = 0.05f / n;
        g_coeff = coeff;
    }
}

// ---- K3: out = x * scale[c] ---------------------------------------------------
// blockIdx.y == 0 -> boost-weight plane; y in [1..C] -> channel c = y-1
// __ldcs reads + __stwt write-through stores (R14-proven)
template <bool EXACT>
__global__ void k_apply(const float* __restrict__ x, float* __restrict__ out, int hw4,
                        const float* __restrict__ bw, float* __restrict__ bwout) {
#if __CUDA_ARCH__ >= 900
    cudaGridDependencySynchronize();   // wait for matvec_stats grid (PDL)
#endif
    if (blockIdx.y == 0) {
        if (bwout) {
            const float coeff = g_coeff;
            const int n4 = (C * C) / 4;                 // 65536 float4
            const int stride = gridDim.x * 256;
            const float4* bw4 = reinterpret_cast<const float4*>(bw);
            float4* bo4 = reinterpret_cast<float4*>(bwout);
            for (int j4 = blockIdx.x * 256 + threadIdx.x; j4 < n4; j4 += stride) {
                const int row  = j4 >> 7;               // 128 float4 per row
                const int col0 = (j4 & 127) << 2;
                float4 w = __ldg(bw4 + j4);
                const float xt = g_xtmp[row];
                float4 r;
                r.x = w.x * 0.5f + ((row == col0    ) ? 0.f : coeff * xt * g_xsparse[col0]);
                r.y = w.y * 0.5f + ((row == col0 + 1) ? 0.f : coeff * xt * g_xsparse[col0 + 1]);
                r.z = w.z * 0.5f + ((row == col0 + 2) ? 0.f : coeff * xt * g_xsparse[col0 + 2]);
                r.w = w.w * 0.5f + ((row == col0 + 3) ? 0.f : coeff * xt * g_xsparse[col0 + 3]);
                bo4[j4] = r;
            }
        }
        return;
    }

    const int c = blockIdx.y - 1;
    const float sc = g_scale[c];
    const size_t base = (size_t)c * hw4;
    const float4* xp = reinterpret_cast<const float4*>(x) + base;
    float4*       op = reinterpret_cast<float4*>(out) + base;

    const int i0 = blockIdx.x * 1024 + threadIdx.x;
    const int i1 = i0 + 256, i2 = i0 + 512, i3 = i0 + 768;

    if (EXACT) {
        float4 v0 = __ldcs(xp + i0);
        float4 v1 = __ldcs(xp + i1);
        float4 v2 = __ldcs(xp + i2);
        float4 v3 = __ldcs(xp + i3);
        v0.x *= sc; v0.y *= sc; v0.z *= sc; v0.w *= sc; __stwt(op + i0, v0);
        v1.x *= sc; v1.y *= sc; v1.z *= sc; v1.w *= sc; __stwt(op + i1, v1);
        v2.x *= sc; v2.y *= sc; v2.z *= sc; v2.w *= sc; __stwt(op + i2, v2);
        v3.x *= sc; v3.y *= sc; v3.z *= sc; v3.w *= sc; __stwt(op + i3, v3);
    } else {
        const bool b0 = i0 < hw4, b1 = i1 < hw4, b2 = i2 < hw4, b3 = i3 < hw4;
        float4 v0, v1, v2, v3;
        if (b0) v0 = __ldcs(xp + i0);
        if (b1) v1 = __ldcs(xp + i1);
        if (b2) v2 = __ldcs(xp + i2);
        if (b3) v3 = __ldcs(xp + i3);
        if (b0) { v0.x *= sc; v0.y *= sc; v0.z *= sc; v0.w *= sc; __stwt(op + i0, v0); }
        if (b1) { v1.x *= sc; v1.y *= sc; v1.z *= sc; v1.w *= sc; __stwt(op + i1, v1); }
        if (b2) { v2.x *= sc; v2.y *= sc; v2.z *= sc; v2.w *= sc; __stwt(op + i2, v2); }
        if (b3) { v3.x *= sc; v3.y *= sc; v3.z *= sc; v3.w *= sc; __stwt(op + i3, v3); }
    }
}

// ---- PDL launch helper ---------------------------------------------------------
template <typename K, typename... Args>
static inline void launch_pdl(dim3 grid, dim3 block, K kernel, Args... args) {
    cudaLaunchConfig_t cfg = {};
    cfg.gridDim  = grid;
    cfg.blockDim = block;
    cudaLaunchAttribute attr[1];
    attr[0].id = cudaLaunchAttributeProgrammaticStreamSerialization;
    attr[0].val.programmaticStreamSerializationAllowed = 1;
    cfg.attrs = attr;
    cfg.numAttrs = 1;
    cudaLaunchKernelEx(&cfg, kernel, args...);
}

// ---- launch -------------------------------------------------------------------
extern "C" void kernel_launch(void* const* d_in, const int* in_sizes, int n_in,
                              void* d_out, int out_size) {
    // identify inputs robustly by size (x is the big one)
    int xi = 0, bi = 1;
    if (n_in >= 2 && in_sizes[0] < in_sizes[1]) { xi = 1; bi = 0; }
    const float* x  = (const float*)d_in[xi];
    const float* bw = (const float*)d_in[bi];
    float* out = (float*)d_out;

    const int n0 = in_sizes[xi];        // 512 * 448 * 448
    const int hw = n0 / C;              // 200704
    const int hw4 = hw >> 2;            // 50176 = 49*1024
    const float inv_hw = 1.0f / (float)hw;

    // mean: NSEG=7 guard-free path (segments of exactly 7*1024 float4, 1024 thr)
    int nseg;
    if (hw4 % (NSEG * 1024) == 0) {
        nseg = NSEG;
        const int seglen = hw4 / NSEG;
        dim3 gmean(NSEG, C);
        k_channel_mean<true><<<gmean, 1024>>>(x, hw4, seglen, NSEG);
    } else {
        nseg = 8;
        const int seglen = (hw4 + nseg - 1) / nseg;
        dim3 gmean(nseg, C);
        k_channel_mean<false><<<gmean, 256>>>(x, hw4, seglen, nseg);
    }

    // matvec + fused last-block stats: PDL-chained after mean
    launch_pdl(dim3(C, 1, 1), dim3(128, 1, 1), k_matvec_stats, bw, inv_hw, nseg);

    float* bwout = (out_size >= n0 + C * C) ? (out + n0) : nullptr;

    // apply + bw plane: PDL-chained after matvec_stats
    if (hw4 % 1024 == 0) {
        launch_pdl(dim3(hw4 / 1024, C + 1, 1), dim3(256, 1, 1),
                   k_apply<true>, x, out, hw4, (const float*)bw, bwout);
    } else {
        launch_pdl(dim3((hw4 + 1023) / 1024, C + 1, 1), dim3(256, 1, 1),
                   k_apply<false>, x, out, hw4, (const float*)bw, bwout);
    }
}

// round 17
// speedup vs baseline: 1.0030x; 1.0030x over previous
#include <cuda_runtime.h>

#define C 512
#define NSEG 7          // 50176/7 = 7168 = 7*1024 -> guard-free fast path
#define NSEG_MAX 8
#define FULLMASK 0xffffffffu

// ---- scratch (no allocs allowed) -------------------------------------------
__device__ float g_part[C][NSEG_MAX];   // partial channel sums
__device__ float g_bv[C];
__device__ float g_xtmp[C];
__device__ float g_xsparse[C];
__device__ float g_scale[C];
__device__ float g_coeff;               // 0.05 / norm (or 0.05 if norm invalid)
__device__ unsigned g_ctr = 0;          // last-block election (never reset; modulo test)

// ---- K1: per-channel partial sums -------------------------------------------
// EXACT path: block=1024 threads, each thread 7 front-batched float4 loads.
// Implicit PDL trigger at grid exit (explicit early trigger measured NEUTRAL:
// the gap saved was repaid in lost occupancy from early-placed waiter CTAs).
template <bool EXACT>
__global__ void k_channel_mean(const float* __restrict__ x, int n4, int seglen, int nseg) {
    const int c   = blockIdx.y;
    const int seg = blockIdx.x;
    const float4* xp = reinterpret_cast<const float4*>(x) + (size_t)c * n4 + (size_t)seg * seglen;

    float s;
    if (EXACT) {
        const int t = threadIdx.x;
        float4 v0 = __ldcs(xp + t);
        float4 v1 = __ldcs(xp + t + 1024);
        float4 v2 = __ldcs(xp + t + 2048);
        float4 v3 = __ldcs(xp + t + 3072);
        float4 v4 = __ldcs(xp + t + 4096);
        float4 v5 = __ldcs(xp + t + 5120);
        float4 v6 = __ldcs(xp + t + 6144);
        float a0 = (v0.x + v0.y) + (v0.z + v0.w);
        float a1 = (v1.x + v1.y) + (v1.z + v1.w);
        float a2 = (v2.x + v2.y) + (v2.z + v2.w);
        float a3 = (v3.x + v3.y) + (v3.z + v3.w);
        float a4 = (v4.x + v4.y) + (v4.z + v4.w);
        float a5 = (v5.x + v5.y) + (v5.z + v5.w);
        float a6 = (v6.x + v6.y) + (v6.z + v6.w);
        s = ((a0 + a1) + (a2 + a3)) + ((a4 + a5) + a6);
    } else {
        const int lim = min(seglen, n4 - seg * seglen);
        float s0 = 0.f, s1 = 0.f, s2 = 0.f, s3 = 0.f;
        for (int i = threadIdx.x; i < lim; i += 4 * blockDim.x) {
            const int i1 = i + blockDim.x, i2 = i + 2 * blockDim.x, i3 = i + 3 * blockDim.x;
            float4 v;
            v = __ldcs(xp + i);                  s0 += (v.x + v.y) + (v.z + v.w);
            if (i1 < lim) { v = __ldcs(xp + i1); s1 += (v.x + v.y) + (v.z + v.w); }
            if (i2 < lim) { v = __ldcs(xp + i2); s2 += (v.x + v.y) + (v.z + v.w); }
            if (i3 < lim) { v = __ldcs(xp + i3); s3 += (v.x + v.y) + (v.z + v.w); }
        }
        s = (s0 + s1) + (s2 + s3);
    }

    __shared__ float sm[32];
    #pragma unroll
    for (int o = 16; o; o >>= 1) s += __shfl_xor_sync(FULLMASK, s, o);
    const int lane = threadIdx.x & 31, w = threadIdx.x >> 5;
    if (lane == 0) sm[w] = s;
    __syncthreads();
    if (threadIdx.x == 0) {
        float t = 0.f;
        const int nw = blockDim.x >> 5;
        for (int k = 0; k < nw; k++) t += sm[k];
        g_part[c][seg] = t;
    }
}

__device__ __forceinline__ float channel_avg(int ch, float inv_hw, int nseg) {
    float t = 0.f;
    #pragma unroll
    for (int k = 0; k < NSEG_MAX; k++)
        if (k < nseg) t += g_part[ch][k];
    return t * inv_hw;
}

// ---- 128-thread (4-warp) block reductions -----------------------------------
__device__ __forceinline__ float blk_sum128(float v, volatile float* sm) {
    #pragma unroll
    for (int o = 16; o; o >>= 1) v += __shfl_xor_sync(FULLMASK, v, o);
    const int lane = threadIdx.x & 31, w = threadIdx.x >> 5;
    if (lane == 0) sm[w] = v;
    __syncthreads();
    float r = (sm[0] + sm[1]) + (sm[2] + sm[3]);
    __syncthreads();
    return r;
}

__device__ __forceinline__ float blk_max128(float v, volatile float* sm) {
    #pragma unroll
    for (int o = 16; o; o >>= 1) v = fmaxf(v, __shfl_xor_sync(FULLMASK, v, o));
    const int lane = threadIdx.x & 31, w = threadIdx.x >> 5;
    if (lane == 0) sm[w] = v;
    __syncthreads();
    float r = fmaxf(fmaxf(sm[0], sm[1]), fmaxf(sm[2], sm[3]));
    __syncthreads();
    return r;
}

// ---- K2: matvec (512 blocks x 128 thr) + last-block stats ---------------------
__global__ void k_matvec_stats(const float* __restrict__ W, float inv_hw, int nseg) {
#if __CUDA_ARCH__ >= 900
    cudaGridDependencySynchronize();   // wait for mean grid (PDL)
#endif
    __shared__ float av[C];
    __shared__ float sm[4];
    __shared__ int   is_last;
    const int t = threadIdx.x;  // 128 threads

    #pragma unroll
    for (int j = t; j < C; j += 128) av[j] = channel_avg(j, inv_hw, nseg);
    __syncthreads();

    const int row = blockIdx.x;
    float4 wv = __ldg(reinterpret_cast<const float4*>(W + (size_t)row * C) + t);
    float s = wv.x * av[4*t] + wv.y * av[4*t+1] + wv.z * av[4*t+2] + wv.w * av[4*t+3];
    #pragma unroll
    for (int o = 16; o; o >>= 1) s += __shfl_xor_sync(FULLMASK, s, o);
    if ((t & 31) == 0) sm[t >> 5] = s;
    __syncthreads();
    if (t == 0) {
        g_bv[row] = (sm[0] + sm[1]) + (sm[2] + sm[3]);
        __threadfence();
        unsigned old = atomicAdd(&g_ctr, 1u);
        is_last = ((old & (C - 1)) == (C - 1)) ? 1 : 0;
    }
    __syncthreads();
    if (!is_last) return;

    // ---- stats: runs in the one block that finished last (sees all g_bv) ----
    __threadfence();
    float a[4], b[4];
    #pragma unroll
    for (int k = 0; k < 4; k++) {
        const int ch = t + 128 * k;
        a[k] = av[ch];
        b[k] = g_bv[ch];
    }

    const float inh = blk_sum128((b[0] + b[1]) + (b[2] + b[3]), sm) * (1.0f / (float)C);

    float xt[4], lmax = -3.4e38f;
    #pragma unroll
    for (int k = 0; k < 4; k++) {
        float v = a[k] + b[k] - 2.0f * inh;
        xt[k] = v > 0.f ? v : 0.f;
        lmax = fmaxf(lmax, xt[k]);
    }
    const float thr = blk_max128(lmax, sm) * 0.9f;

    float xs[4];
    float lst2 = 0.f, lss2 = 0.f, lsd2 = 0.f;
    #pragma unroll
    for (int k = 0; k < 4; k++) {
        const int ch = t + 128 * k;
        xs[k] = (xt[k] < thr) ? 0.f : xt[k];
        g_xtmp[ch]    = xt[k];
        g_xsparse[ch] = xs[k];
        g_scale[ch]   = xt[k] / (a[k] + 1e-12f);
        lst2 += xt[k] * xt[k];
        lss2 += xs[k] * xs[k];
        const float ts = xt[k] * xs[k];
        lsd2 += ts * ts;
    }
    const float st2 = blk_sum128(lst2, sm);
    const float ss2 = blk_sum128(lss2, sm);
    const float sd2 = blk_sum128(lsd2, sm);

    if (t == 0) {
        const float n2 = st2 * ss2 - sd2;             // ||outer zero-diag||_F^2
        const float n  = sqrtf(n2);
        float coeff = 0.05f;
        if (isfinite(n) && n > 0.f) coeff = 0.05f / n;
        g_coeff = coeff;
    }
}

// ---- K3: out = x * scale[c] ---------------------------------------------------
// blockIdx.y == 0 -> boost-weight plane; y in [1..C] -> channel c = y-1
// __ldcs reads + __stwt write-through stores (R14-proven)
template <bool EXACT>
__global__ void k_apply(const float* __restrict__ x, float* __restrict__ out, int hw4,
                        const float* __restrict__ bw, float* __restrict__ bwout) {
#if __CUDA_ARCH__ >= 900
    cudaGridDependencySynchronize();   // wait for matvec_stats grid (PDL)
#endif
    if (blockIdx.y == 0) {
        if (bwout) {
            const float coeff = g_coeff;
            const int n4 = (C * C) / 4;                 // 65536 float4
            const int stride = gridDim.x * 256;
            const float4* bw4 = reinterpret_cast<const float4*>(bw);
            float4* bo4 = reinterpret_cast<float4*>(bwout);
            for (int j4 = blockIdx.x * 256 + threadIdx.x; j4 < n4; j4 += stride) {
                const int row  = j4 >> 7;               // 128 float4 per row
                const int col0 = (j4 & 127) << 2;
                float4 w = __ldg(bw4 + j4);
                const float xt = g_xtmp[row];
                float4 r;
                r.x = w.x * 0.5f + ((row == col0    ) ? 0.f : coeff * xt * g_xsparse[col0]);
                r.y = w.y * 0.5f + ((row == col0 + 1) ? 0.f : coeff * xt * g_xsparse[col0 + 1]);
                r.z = w.z * 0.5f + ((row == col0 + 2) ? 0.f : coeff * xt * g_xsparse[col0 + 2]);
                r.w = w.w * 0.5f + ((row == col0 + 3) ? 0.f : coeff * xt * g_xsparse[col0 + 3]);
                bo4[j4] = r;
            }
        }
        return;
    }

    const int c = blockIdx.y - 1;
    const float sc = g_scale[c];
    const size_t base = (size_t)c * hw4;
    const float4* xp = reinterpret_cast<const float4*>(x) + base;
    float4*       op = reinterpret_cast<float4*>(out) + base;

    const int i0 = blockIdx.x * 1024 + threadIdx.x;
    const int i1 = i0 + 256, i2 = i0 + 512, i3 = i0 + 768;

    if (EXACT) {
        float4 v0 = __ldcs(xp + i0);
        float4 v1 = __ldcs(xp + i1);
        float4 v2 = __ldcs(xp + i2);
        float4 v3 = __ldcs(xp + i3);
        v0.x *= sc; v0.y *= sc; v0.z *= sc; v0.w *= sc; __stwt(op + i0, v0);
        v1.x *= sc; v1.y *= sc; v1.z *= sc; v1.w *= sc; __stwt(op + i1, v1);
        v2.x *= sc; v2.y *= sc; v2.z *= sc; v2.w *= sc; __stwt(op + i2, v2);
        v3.x *= sc; v3.y *= sc; v3.z *= sc; v3.w *= sc; __stwt(op + i3, v3);
    } else {
        const bool b0 = i0 < hw4, b1 = i1 < hw4, b2 = i2 < hw4, b3 = i3 < hw4;
        float4 v0, v1, v2, v3;
        if (b0) v0 = __ldcs(xp + i0);
        if (b1) v1 = __ldcs(xp + i1);
        if (b2) v2 = __ldcs(xp + i2);
        if (b3) v3 = __ldcs(xp + i3);
        if (b0) { v0.x *= sc; v0.y *= sc; v0.z *= sc; v0.w *= sc; __stwt(op + i0, v0); }
        if (b1) { v1.x *= sc; v1.y *= sc; v1.z *= sc; v1.w *= sc; __stwt(op + i1, v1); }
        if (b2) { v2.x *= sc; v2.y *= sc; v2.z *= sc; v2.w *= sc; __stwt(op + i2, v2); }
        if (b3) { v3.x *= sc; v3.y *= sc; v3.z *= sc; v3.w *= sc; __stwt(op + i3, v3); }
    }
}

// ---- PDL launch helper ---------------------------------------------------------
template <typename K, typename... Args>
static inline void launch_pdl(dim3 grid, dim3 block, K kernel, Args... args) {
    cudaLaunchConfig_t cfg = {};
    cfg.gridDim  = grid;
    cfg.blockDim = block;
    cudaLaunchAttribute attr[1];
    attr[0].id = cudaLaunchAttributeProgrammaticStreamSerialization;
    attr[0].val.programmaticStreamSerializationAllowed = 1;
    cfg.attrs = attr;
    cfg.numAttrs = 1;
    cudaLaunchKernelEx(&cfg, kernel, args...);
}

// ---- launch -------------------------------------------------------------------
extern "C" void kernel_launch(void* const* d_in, const int* in_sizes, int n_in,
                              void* d_out, int out_size) {
    // identify inputs robustly by size (x is the big one)
    int xi = 0, bi = 1;
    if (n_in >= 2 && in_sizes[0] < in_sizes[1]) { xi = 1; bi = 0; }
    const float* x  = (const float*)d_in[xi];
    const float* bw = (const float*)d_in[bi];
    float* out = (float*)d_out;

    const int n0 = in_sizes[xi];        // 512 * 448 * 448
    const int hw = n0 / C;              // 200704
    const int hw4 = hw >> 2;            // 50176 = 49*1024
    const float inv_hw = 1.0f / (float)hw;

    // mean: NSEG=7 guard-free path (segments of exactly 7*1024 float4, 1024 thr)
    int nseg;
    if (hw4 % (NSEG * 1024) == 0) {
        nseg = NSEG;
        const int seglen = hw4 / NSEG;
        dim3 gmean(NSEG, C);
        k_channel_mean<true><<<gmean, 1024>>>(x, hw4, seglen, NSEG);
    } else {
        nseg = 8;
        const int seglen = (hw4 + nseg - 1) / nseg;
        dim3 gmean(nseg, C);
        k_channel_mean<false><<<gmean, 256>>>(x, hw4, seglen, nseg);
    }

    // matvec + fused last-block stats: PDL-chained after mean
    launch_pdl(dim3(C, 1, 1), dim3(128, 1, 1), k_matvec_stats, bw, inv_hw, nseg);

    float* bwout = (out_size >= n0 + C * C) ? (out + n0) : nullptr;

    // apply + bw plane: PDL-chained after matvec_stats
    if (hw4 % 1024 == 0) {
        launch_pdl(dim3(hw4 / 1024, C + 1, 1), dim3(256, 1, 1),
                   k_apply<true>, x, out, hw4, (const float*)bw, bwout);
    } else {
        launch_pdl(dim3((hw4 + 1023) / 1024, C + 1, 1), dim3(256, 1, 1),
                   k_apply<false>, x, out, hw4, (const float*)bw, bwout);
    }
}